// round 1
// baseline (speedup 1.0000x reference)
#include <cuda_runtime.h>
#include <math.h>
#include <math_constants.h>

// Problem constants
#define Bq  2
#define Tq  1024
#define Dq  1024
#define Hq  16
#define FFq 4096
#define Lq  8
#define Vq  32000
#define HDq 64
#define Rq  (Bq * Tq)   // 2048 rows

// ---------------------------------------------------------------------------
// Scratch (device globals; no runtime allocation allowed)
// ---------------------------------------------------------------------------
__device__ float g_x  [Rq * Dq];       // residual stream
__device__ float g_ln [Rq * Dq];       // layernorm output
__device__ float g_qkv[Rq * 3 * Dq];   // q|k|v
__device__ float g_y  [Rq * Dq];       // attention output
__device__ float g_ff [Rq * FFq];      // mlp hidden

// ---------------------------------------------------------------------------
// Block reductions
// ---------------------------------------------------------------------------
__device__ __forceinline__ float block_sum(float v, float* sh) {
    int lane = threadIdx.x & 31, w = threadIdx.x >> 5, nw = blockDim.x >> 5;
    #pragma unroll
    for (int o = 16; o; o >>= 1) v += __shfl_xor_sync(0xffffffffu, v, o);
    if (lane == 0) sh[w] = v;
    __syncthreads();
    if (w == 0) {
        v = (lane < nw) ? sh[lane] : 0.0f;
        #pragma unroll
        for (int o = 16; o; o >>= 1) v += __shfl_xor_sync(0xffffffffu, v, o);
        if (lane == 0) sh[0] = v;
    }
    __syncthreads();
    float r = sh[0];
    __syncthreads();
    return r;
}

__device__ __forceinline__ float block_max(float v, float* sh) {
    int lane = threadIdx.x & 31, w = threadIdx.x >> 5, nw = blockDim.x >> 5;
    #pragma unroll
    for (int o = 16; o; o >>= 1) v = fmaxf(v, __shfl_xor_sync(0xffffffffu, v, o));
    if (lane == 0) sh[w] = v;
    __syncthreads();
    if (w == 0) {
        v = (lane < nw) ? sh[lane] : -CUDART_INF_F;
        #pragma unroll
        for (int o = 16; o; o >>= 1) v = fmaxf(v, __shfl_xor_sync(0xffffffffu, v, o));
        if (lane == 0) sh[0] = v;
    }
    __syncthreads();
    float r = sh[0];
    __syncthreads();
    return r;
}

// ---------------------------------------------------------------------------
// Embedding + sinusoidal PE
// ---------------------------------------------------------------------------
__global__ void embed_kernel(const int* __restrict__ idx,
                             const float* __restrict__ emb,
                             float* __restrict__ x) {
    int row = blockIdx.x;           // 0..2047  (b*T + t)
    int t   = row % Tq;
    int tok = idx[row];
    const float* er = emb + (size_t)tok * Dq;
    const float neg_log = -logf(10000.0f) / (float)Dq;
    for (int d = threadIdx.x; d < Dq; d += blockDim.x) {
        int i2 = d & ~1;                     // even index 0,2,4,...
        float freq = expf(neg_log * (float)i2);
        float ang  = (float)t * freq;
        float pe   = (d & 1) ? cosf(ang) : sinf(ang);
        x[(size_t)row * Dq + d] = er[d] + pe;
    }
}

// ---------------------------------------------------------------------------
// LayerNorm (two-pass, 256 threads, 4 elems/thread, D=1024)
// ---------------------------------------------------------------------------
__global__ void ln_kernel(const float* __restrict__ x,
                          const float* __restrict__ sc,
                          const float* __restrict__ bi,
                          float* __restrict__ out) {
    __shared__ float sh[32];
    int row = blockIdx.x;
    const float* xr = x + (size_t)row * Dq;
    float v[4];
    float lsum = 0.0f;
    #pragma unroll
    for (int i = 0; i < 4; i++) {
        v[i] = xr[threadIdx.x + i * 256];
        lsum += v[i];
    }
    float mean = block_sum(lsum, sh) * (1.0f / (float)Dq);
    float lsq = 0.0f;
    #pragma unroll
    for (int i = 0; i < 4; i++) {
        float d = v[i] - mean;
        lsq += d * d;
    }
    float var = block_sum(lsq, sh) * (1.0f / (float)Dq);
    float inv = rsqrtf(var + 1e-5f);
    #pragma unroll
    for (int i = 0; i < 4; i++) {
        int d = threadIdx.x + i * 256;
        out[(size_t)row * Dq + d] = (v[i] - mean) * inv * sc[d] + bi[d];
    }
}

// ---------------------------------------------------------------------------
// SGEMM:  C[M,N] = A[M,K] @ B[K,N] (+ bias) with epilogue modes
//   EPI 0: C = AB + bias
//   EPI 1: C += AB + bias          (residual accumulate)
//   EPI 2: C = gelu(AB + bias)     (exact erf gelu)
// 128x128 tile, BK=8, 256 threads, 8x8 per thread.
// Requires M%128==0, N%128==0, K%8==0 (true for all our shapes).
// ---------------------------------------------------------------------------
template <int EPI>
__global__ __launch_bounds__(256)
void sgemm_kernel(const float* __restrict__ A, const float* __restrict__ B,
                  const float* __restrict__ bias, float* __restrict__ C,
                  int M, int N, int K) {
    constexpr int BM = 128, BN = 128, BK = 8, TM = 8, TN = 8;
    __shared__ float As[BK][BM];
    __shared__ float Bs[BK][BN];

    int tid = threadIdx.x;
    int tx = tid & 15;          // 0..15 (N dir)
    int ty = tid >> 4;          // 0..15 (M dir)

    int arow = tid >> 1;               // 0..127
    int acol = (tid & 1) * 4;          // 0 or 4
    int brow = tid >> 5;               // 0..7
    int bcol = (tid & 31) * 4;         // 0..124

    const float* Ab = A + (size_t)(blockIdx.y * BM) * K;
    const float* Bb = B + (size_t)(blockIdx.x) * BN;

    float acc[TM][TN];
    #pragma unroll
    for (int i = 0; i < TM; i++)
        #pragma unroll
        for (int j = 0; j < TN; j++) acc[i][j] = 0.0f;

    for (int k0 = 0; k0 < K; k0 += BK) {
        float4 av = *(const float4*)(Ab + (size_t)arow * K + k0 + acol);
        As[acol + 0][arow] = av.x;
        As[acol + 1][arow] = av.y;
        As[acol + 2][arow] = av.z;
        As[acol + 3][arow] = av.w;
        float4 bv = *(const float4*)(Bb + (size_t)(k0 + brow) * N + bcol);
        *(float4*)&Bs[brow][bcol] = bv;
        __syncthreads();

        #pragma unroll
        for (int kk = 0; kk < BK; kk++) {
            float ar[TM], br[TN];
            #pragma unroll
            for (int i = 0; i < TM; i++) ar[i] = As[kk][ty * TM + i];
            #pragma unroll
            for (int j = 0; j < TN; j++) br[j] = Bs[kk][tx * TN + j];
            #pragma unroll
            for (int i = 0; i < TM; i++)
                #pragma unroll
                for (int j = 0; j < TN; j++)
                    acc[i][j] += ar[i] * br[j];
        }
        __syncthreads();
    }

    int row0 = blockIdx.y * BM + ty * TM;
    int col0 = blockIdx.x * BN + tx * TN;
    float bv[TN];
    #pragma unroll
    for (int j = 0; j < TN; j++) bv[j] = bias ? bias[col0 + j] : 0.0f;

    #pragma unroll
    for (int i = 0; i < TM; i++) {
        size_t off = (size_t)(row0 + i) * N + col0;
        #pragma unroll
        for (int j = 0; j < TN; j++) {
            float val = acc[i][j] + bv[j];
            if (EPI == 0) {
                C[off + j] = val;
            } else if (EPI == 1) {
                C[off + j] += val;
            } else {
                C[off + j] = 0.5f * val * (1.0f + erff(val * 0.70710678118654752f));
            }
        }
    }
}

// ---------------------------------------------------------------------------
// Causal attention, one block per (t, h, b). 128 threads.
// qkv layout: row = b*T + t, cols [0,D)=q [D,2D)=k [2D,3D)=v ; head slice h*64.
// ---------------------------------------------------------------------------
__global__ __launch_bounds__(128)
void attn_kernel(const float* __restrict__ qkv, float* __restrict__ y) {
    __shared__ float scs[Tq];
    __shared__ float qs[HDq];
    __shared__ float red[32];
    __shared__ float accu[HDq];

    int t = blockIdx.x, h = blockIdx.y, b = blockIdx.z;
    int tid = threadIdx.x;

    const float* qrow = qkv + ((size_t)(b * Tq + t)) * (3 * Dq) + h * HDq;
    if (tid < HDq) qs[tid] = qrow[tid];
    __syncthreads();

    int nk = t + 1;
    float lmax = -CUDART_INF_F;
    for (int s = tid; s < nk; s += 128) {
        const float4* kr = (const float4*)(qkv + ((size_t)(b * Tq + s)) * (3 * Dq) + Dq + h * HDq);
        float a = 0.0f;
        #pragma unroll
        for (int i = 0; i < HDq / 4; i++) {
            float4 kv = kr[i];
            a += qs[4*i+0] * kv.x + qs[4*i+1] * kv.y + qs[4*i+2] * kv.z + qs[4*i+3] * kv.w;
        }
        a *= 0.125f;   // 1/sqrt(64)
        scs[s] = a;
        lmax = fmaxf(lmax, a);
    }
    float m = block_max(lmax, red);

    float lsum = 0.0f;
    for (int s = tid; s < nk; s += 128) {
        float p = expf(scs[s] - m);
        scs[s] = p;
        lsum += p;
    }
    float ssum = block_sum(lsum, red);  // contains __syncthreads -> scs visible
    float inv = 1.0f / ssum;

    // P @ V : 64 dims, two halves of threads split the s range
    int d = tid & 63, half = tid >> 6;
    float a = 0.0f;
    const float* vbase = qkv + 2 * Dq + h * HDq + d;
    for (int s = half; s < nk; s += 2) {
        a += scs[s] * vbase[((size_t)(b * Tq + s)) * (3 * Dq)];
    }
    if (half == 1) accu[d] = a;
    __syncthreads();
    if (half == 0) {
        y[((size_t)(b * Tq + t)) * Dq + h * HDq + d] = (a + accu[d]) * inv;
    }
}

// ---------------------------------------------------------------------------
// Launch
// ---------------------------------------------------------------------------
extern "C" void kernel_launch(void* const* d_in, const int* in_sizes, int n_in,
                              void* d_out, int out_size) {
    const int*   idx     = (const int*)  d_in[0];
    const float* tok_emb = (const float*)d_in[1];
    const float* ln1_s   = (const float*)d_in[2];
    const float* ln1_b   = (const float*)d_in[3];
    const float* qkv_w   = (const float*)d_in[4];
    const float* qkv_b   = (const float*)d_in[5];
    const float* out_w   = (const float*)d_in[6];
    const float* out_b   = (const float*)d_in[7];
    const float* ln2_s   = (const float*)d_in[8];
    const float* ln2_b   = (const float*)d_in[9];
    const float* mlp_w1  = (const float*)d_in[10];
    const float* mlp_b1  = (const float*)d_in[11];
    const float* mlp_w2  = (const float*)d_in[12];
    const float* mlp_b2  = (const float*)d_in[13];
    const float* lnf_s   = (const float*)d_in[14];
    const float* lnf_b   = (const float*)d_in[15];
    const float* head_w  = (const float*)d_in[16];
    float* logits = (float*)d_out;

    float *x, *ln, *qkv, *y, *ff;
    cudaGetSymbolAddress((void**)&x,   g_x);
    cudaGetSymbolAddress((void**)&ln,  g_ln);
    cudaGetSymbolAddress((void**)&qkv, g_qkv);
    cudaGetSymbolAddress((void**)&y,   g_y);
    cudaGetSymbolAddress((void**)&ff,  g_ff);

    embed_kernel<<<Rq, 256>>>(idx, tok_emb, x);

    for (int l = 0; l < Lq; l++) {
        // h = LN1(x)
        ln_kernel<<<Rq, 256>>>(x, ln1_s + (size_t)l * Dq, ln1_b + (size_t)l * Dq, ln);
        // qkv = h @ Wqkv + bqkv   [2048,1024]x[1024,3072]
        sgemm_kernel<0><<<dim3(3 * Dq / 128, Rq / 128), 256>>>(
            ln, qkv_w + (size_t)l * Dq * 3 * Dq, qkv_b + (size_t)l * 3 * Dq,
            qkv, Rq, 3 * Dq, Dq);
        // causal attention
        attn_kernel<<<dim3(Tq, Hq, Bq), 128>>>(qkv, y);
        // x += y @ Wo + bo
        sgemm_kernel<1><<<dim3(Dq / 128, Rq / 128), 256>>>(
            y, out_w + (size_t)l * Dq * Dq, out_b + (size_t)l * Dq,
            x, Rq, Dq, Dq);
        // h2 = LN2(x)
        ln_kernel<<<Rq, 256>>>(x, ln2_s + (size_t)l * Dq, ln2_b + (size_t)l * Dq, ln);
        // ff = gelu(h2 @ W1 + b1)   [2048,1024]x[1024,4096]
        sgemm_kernel<2><<<dim3(FFq / 128, Rq / 128), 256>>>(
            ln, mlp_w1 + (size_t)l * Dq * FFq, mlp_b1 + (size_t)l * FFq,
            ff, Rq, FFq, Dq);
        // x += ff @ W2 + b2   [2048,4096]x[4096,1024]
        sgemm_kernel<1><<<dim3(Dq / 128, Rq / 128), 256>>>(
            ff, mlp_w2 + (size_t)l * FFq * Dq, mlp_b2 + (size_t)l * Dq,
            x, Rq, Dq, FFq);
    }

    // final LN + head
    ln_kernel<<<Rq, 256>>>(x, lnf_s, lnf_b, ln);
    sgemm_kernel<0><<<dim3(Vq / 128, Rq / 128), 256>>>(
        ln, head_w, (const float*)nullptr, logits, Rq, Vq, Dq);
}

// round 3
// speedup vs baseline: 1.5558x; 1.5558x over previous
#include <cuda_runtime.h>
#include <math.h>
#include <math_constants.h>

// Problem constants
#define Bq  2
#define Tq  1024
#define Dq  1024
#define Hq  16
#define FFq 4096
#define Lq  8
#define Vq  32000
#define HDq 64
#define Rq  (Bq * Tq)   // 2048 rows

// ---------------------------------------------------------------------------
// Scratch (device globals; no runtime allocation allowed)
// ---------------------------------------------------------------------------
__device__ float g_x  [Rq * Dq];       // residual stream
__device__ float g_ln [Rq * Dq];       // layernorm output
__device__ float g_qkv[Rq * 3 * Dq];   // q|k|v
__device__ float g_y  [Rq * Dq];       // attention output
__device__ float g_ff [Rq * FFq];      // mlp hidden

// ---------------------------------------------------------------------------
// Block reductions
// ---------------------------------------------------------------------------
__device__ __forceinline__ float block_sum(float v, float* sh) {
    int lane = threadIdx.x & 31, w = threadIdx.x >> 5, nw = blockDim.x >> 5;
    #pragma unroll
    for (int o = 16; o; o >>= 1) v += __shfl_xor_sync(0xffffffffu, v, o);
    if (lane == 0) sh[w] = v;
    __syncthreads();
    if (w == 0) {
        v = (lane < nw) ? sh[lane] : 0.0f;
        #pragma unroll
        for (int o = 16; o; o >>= 1) v += __shfl_xor_sync(0xffffffffu, v, o);
        if (lane == 0) sh[0] = v;
    }
    __syncthreads();
    float r = sh[0];
    __syncthreads();
    return r;
}

__device__ __forceinline__ float block_max(float v, float* sh) {
    int lane = threadIdx.x & 31, w = threadIdx.x >> 5, nw = blockDim.x >> 5;
    #pragma unroll
    for (int o = 16; o; o >>= 1) v = fmaxf(v, __shfl_xor_sync(0xffffffffu, v, o));
    if (lane == 0) sh[w] = v;
    __syncthreads();
    if (w == 0) {
        v = (lane < nw) ? sh[lane] : -CUDART_INF_F;
        #pragma unroll
        for (int o = 16; o; o >>= 1) v = fmaxf(v, __shfl_xor_sync(0xffffffffu, v, o));
        if (lane == 0) sh[0] = v;
    }
    __syncthreads();
    float r = sh[0];
    __syncthreads();
    return r;
}

// ---------------------------------------------------------------------------
// Embedding + sinusoidal PE
// ---------------------------------------------------------------------------
__global__ void embed_kernel(const int* __restrict__ idx,
                             const float* __restrict__ emb,
                             float* __restrict__ x) {
    int row = blockIdx.x;           // 0..2047  (b*T + t)
    int t   = row % Tq;
    int tok = idx[row];
    const float* er = emb + (size_t)tok * Dq;
    const float neg_log = -logf(10000.0f) / (float)Dq;
    for (int d = threadIdx.x; d < Dq; d += blockDim.x) {
        int i2 = d & ~1;                     // even index 0,2,4,...
        float freq = expf(neg_log * (float)i2);
        float ang  = (float)t * freq;
        float pe   = (d & 1) ? cosf(ang) : sinf(ang);
        x[(size_t)row * Dq + d] = er[d] + pe;
    }
}

// ---------------------------------------------------------------------------
// LayerNorm (two-pass, 256 threads, 4 elems/thread, D=1024)
// ---------------------------------------------------------------------------
__global__ void ln_kernel(const float* __restrict__ x,
                          const float* __restrict__ sc,
                          const float* __restrict__ bi,
                          float* __restrict__ out) {
    __shared__ float sh[32];
    int row = blockIdx.x;
    const float* xr = x + (size_t)row * Dq;
    float v[4];
    float lsum = 0.0f;
    #pragma unroll
    for (int i = 0; i < 4; i++) {
        v[i] = xr[threadIdx.x + i * 256];
        lsum += v[i];
    }
    float mean = block_sum(lsum, sh) * (1.0f / (float)Dq);
    float lsq = 0.0f;
    #pragma unroll
    for (int i = 0; i < 4; i++) {
        float d = v[i] - mean;
        lsq += d * d;
    }
    float var = block_sum(lsq, sh) * (1.0f / (float)Dq);
    float inv = rsqrtf(var + 1e-5f);
    #pragma unroll
    for (int i = 0; i < 4; i++) {
        int d = threadIdx.x + i * 256;
        out[(size_t)row * Dq + d] = (v[i] - mean) * inv * sc[d] + bi[d];
    }
}

// ---------------------------------------------------------------------------
// TF32 tensor-core GEMM:  C[M,N] = A[M,K] @ B[K,N] (+ bias), epilogues:
//   EPI 0: C = AB + bias
//   EPI 1: C += AB + bias          (residual accumulate)
//   EPI 2: C = gelu(AB + bias)     (exact erf gelu)
// 128x128 tile, BK=32, 256 threads (8 warps, 2x4), warp tile 64x32,
// mma.sync.m16n8k8 tf32 with fp32 accumulate. XOR-swizzled smem.
// Requires M%128==0, N%128==0, K%32==0 (true for all our shapes).
// ---------------------------------------------------------------------------
__device__ __forceinline__ unsigned f2tf(float x) {
    unsigned r;
    asm("cvt.rna.tf32.f32 %0, %1;" : "=r"(r) : "f"(x));
    return r;
}

__device__ __forceinline__ void mma_tf32(float c[4],
                                         unsigned a0, unsigned a1, unsigned a2, unsigned a3,
                                         unsigned b0, unsigned b1) {
    asm volatile(
        "mma.sync.aligned.m16n8k8.row.col.f32.tf32.tf32.f32 "
        "{%0,%1,%2,%3}, {%4,%5,%6,%7}, {%8,%9}, {%0,%1,%2,%3};"
        : "+f"(c[0]), "+f"(c[1]), "+f"(c[2]), "+f"(c[3])
        : "r"(a0), "r"(a1), "r"(a2), "r"(a3), "r"(b0), "r"(b1));
}

template <int EPI>
__global__ __launch_bounds__(256)
void tgemm_kernel(const float* __restrict__ A, const float* __restrict__ B,
                  const float* __restrict__ bias, float* __restrict__ C,
                  int M, int N, int K) {
    constexpr int BM = 128, BN = 128, BK = 32;
    __shared__ unsigned As[BK][BM];   // [k][m ^ ((k&3)<<3)]
    __shared__ unsigned Bs[BK][BN];   // [k][n ^ ((k&3)<<3)]

    int tid  = threadIdx.x;
    int lane = tid & 31;
    int warp = tid >> 5;
    int g    = lane >> 2;       // group 0..7
    int tig  = lane & 3;        // thread-in-group 0..3
    int sw   = tig << 3;        // fragment XOR swizzle
    int wm   = warp & 1;        // warp M index (0..1)
    int wn   = warp >> 1;       // warp N index (0..3)
    int rm   = wm * 64;         // warp row offset in tile
    int cn   = wn * 32;         // warp col offset in tile

    const float* Ab = A + (size_t)(blockIdx.y * BM) * K;
    const float* Bb = B + (size_t)(blockIdx.x) * BN;

    float acc[4][4][4];
    #pragma unroll
    for (int mi = 0; mi < 4; mi++)
        #pragma unroll
        for (int ni = 0; ni < 4; ni++)
            #pragma unroll
            for (int c = 0; c < 4; c++) acc[mi][ni][c] = 0.0f;

    for (int kt = 0; kt < K; kt += BK) {
        // ---- load A tile 128x32 (row-major source, k-major swizzled smem) ----
        #pragma unroll
        for (int i = 0; i < 4; i++) {
            int lin = tid + i * 256;
            int m   = lin >> 3;
            int kq  = (lin & 7) * 4;
            float4 v = *(const float4*)(Ab + (size_t)m * K + kt + kq);
            As[kq + 0][m ^ 0 ] = f2tf(v.x);
            As[kq + 1][m ^ 8 ] = f2tf(v.y);
            As[kq + 2][m ^ 16] = f2tf(v.z);
            As[kq + 3][m ^ 24] = f2tf(v.w);
        }
        // ---- load B tile 32x128 ----
        #pragma unroll
        for (int i = 0; i < 4; i++) {
            int lin = tid + i * 256;
            int kk  = lin >> 5;
            int c4  = (lin & 31) * 4;
            float4 v = *(const float4*)(Bb + (size_t)(kt + kk) * N + c4);
            uint4 u;
            u.x = f2tf(v.x); u.y = f2tf(v.y); u.z = f2tf(v.z); u.w = f2tf(v.w);
            *(uint4*)&Bs[kk][c4 ^ ((kk & 3) << 3)] = u;
        }
        __syncthreads();

        // ---- compute: 4 k-steps of 8 ----
        #pragma unroll
        for (int ks = 0; ks < 4; ks++) {
            int k0 = ks * 8;
            unsigned af[4][4], bf[4][2];
            #pragma unroll
            for (int mi = 0; mi < 4; mi++) {
                int m1 = rm + mi * 16 + g;
                int m2 = m1 + 8;
                af[mi][0] = As[k0 + tig    ][m1 ^ sw];
                af[mi][1] = As[k0 + tig    ][m2 ^ sw];
                af[mi][2] = As[k0 + tig + 4][m1 ^ sw];
                af[mi][3] = As[k0 + tig + 4][m2 ^ sw];
            }
            #pragma unroll
            for (int ni = 0; ni < 4; ni++) {
                int nb = cn + ni * 8 + g;
                bf[ni][0] = Bs[k0 + tig    ][nb ^ sw];
                bf[ni][1] = Bs[k0 + tig + 4][nb ^ sw];
            }
            #pragma unroll
            for (int mi = 0; mi < 4; mi++)
                #pragma unroll
                for (int ni = 0; ni < 4; ni++)
                    mma_tf32(acc[mi][ni],
                             af[mi][0], af[mi][1], af[mi][2], af[mi][3],
                             bf[ni][0], bf[ni][1]);
        }
        __syncthreads();
    }

    // ---- epilogue ----
    #pragma unroll
    for (int ni = 0; ni < 4; ni++) {
        int gc = blockIdx.x * BN + cn + ni * 8 + 2 * tig;
        float bv0 = bias ? bias[gc]     : 0.0f;
        float bv1 = bias ? bias[gc + 1] : 0.0f;
        #pragma unroll
        for (int mi = 0; mi < 4; mi++) {
            int gr1 = blockIdx.y * BM + rm + mi * 16 + g;
            int gr2 = gr1 + 8;
            float v00 = acc[mi][ni][0] + bv0;
            float v01 = acc[mi][ni][1] + bv1;
            float v10 = acc[mi][ni][2] + bv0;
            float v11 = acc[mi][ni][3] + bv1;
            float* p1 = C + (size_t)gr1 * N + gc;
            float* p2 = C + (size_t)gr2 * N + gc;
            if (EPI == 0) {
                *(float2*)p1 = make_float2(v00, v01);
                *(float2*)p2 = make_float2(v10, v11);
            } else if (EPI == 1) {
                float2 o1 = *(const float2*)p1;
                float2 o2 = *(const float2*)p2;
                *(float2*)p1 = make_float2(o1.x + v00, o1.y + v01);
                *(float2*)p2 = make_float2(o2.x + v10, o2.y + v11);
            } else {
                const float inv_sqrt2 = 0.70710678118654752f;
                *(float2*)p1 = make_float2(
                    0.5f * v00 * (1.0f + erff(v00 * inv_sqrt2)),
                    0.5f * v01 * (1.0f + erff(v01 * inv_sqrt2)));
                *(float2*)p2 = make_float2(
                    0.5f * v10 * (1.0f + erff(v10 * inv_sqrt2)),
                    0.5f * v11 * (1.0f + erff(v11 * inv_sqrt2)));
            }
        }
    }
}

// ---------------------------------------------------------------------------
// Causal attention, one block per (t, h, b). 128 threads.
// qkv layout: row = b*T + t, cols [0,D)=q [D,2D)=k [2D,3D)=v ; head slice h*64.
// ---------------------------------------------------------------------------
__global__ __launch_bounds__(128)
void attn_kernel(const float* __restrict__ qkv, float* __restrict__ y) {
    __shared__ float scs[Tq];
    __shared__ float qs[HDq];
    __shared__ float red[32];
    __shared__ float accu[HDq];

    int t = blockIdx.x, h = blockIdx.y, b = blockIdx.z;
    int tid = threadIdx.x;

    const float* qrow = qkv + ((size_t)(b * Tq + t)) * (3 * Dq) + h * HDq;
    if (tid < HDq) qs[tid] = qrow[tid];
    __syncthreads();

    int nk = t + 1;
    float lmax = -CUDART_INF_F;
    for (int s = tid; s < nk; s += 128) {
        const float4* kr = (const float4*)(qkv + ((size_t)(b * Tq + s)) * (3 * Dq) + Dq + h * HDq);
        float a = 0.0f;
        #pragma unroll
        for (int i = 0; i < HDq / 4; i++) {
            float4 kv = kr[i];
            a += qs[4*i+0] * kv.x + qs[4*i+1] * kv.y + qs[4*i+2] * kv.z + qs[4*i+3] * kv.w;
        }
        a *= 0.125f;   // 1/sqrt(64)
        scs[s] = a;
        lmax = fmaxf(lmax, a);
    }
    float m = block_max(lmax, red);

    float lsum = 0.0f;
    for (int s = tid; s < nk; s += 128) {
        float p = expf(scs[s] - m);
        scs[s] = p;
        lsum += p;
    }
    float ssum = block_sum(lsum, red);  // contains __syncthreads -> scs visible
    float inv = 1.0f / ssum;

    // P @ V : 64 dims, two halves of threads split the s range
    int d = tid & 63, half = tid >> 6;
    float a = 0.0f;
    const float* vbase = qkv + 2 * Dq + h * HDq + d;
    for (int s = half; s < nk; s += 2) {
        a += scs[s] * vbase[((size_t)(b * Tq + s)) * (3 * Dq)];
    }
    if (half == 1) accu[d] = a;
    __syncthreads();
    if (half == 0) {
        y[((size_t)(b * Tq + t)) * Dq + h * HDq + d] = (a + accu[d]) * inv;
    }
}

// ---------------------------------------------------------------------------
// Launch
// ---------------------------------------------------------------------------
extern "C" void kernel_launch(void* const* d_in, const int* in_sizes, int n_in,
                              void* d_out, int out_size) {
    const int*   idx     = (const int*)  d_in[0];
    const float* tok_emb = (const float*)d_in[1];
    const float* ln1_s   = (const float*)d_in[2];
    const float* ln1_b   = (const float*)d_in[3];
    const float* qkv_w   = (const float*)d_in[4];
    const float* qkv_b   = (const float*)d_in[5];
    const float* out_w   = (const float*)d_in[6];
    const float* out_b   = (const float*)d_in[7];
    const float* ln2_s   = (const float*)d_in[8];
    const float* ln2_b   = (const float*)d_in[9];
    const float* mlp_w1  = (const float*)d_in[10];
    const float* mlp_b1  = (const float*)d_in[11];
    const float* mlp_w2  = (const float*)d_in[12];
    const float* mlp_b2  = (const float*)d_in[13];
    const float* lnf_s   = (const float*)d_in[14];
    const float* lnf_b   = (const float*)d_in[15];
    const float* head_w  = (const float*)d_in[16];
    float* logits = (float*)d_out;

    float *x, *ln, *qkv, *y, *ff;
    cudaGetSymbolAddress((void**)&x,   g_x);
    cudaGetSymbolAddress((void**)&ln,  g_ln);
    cudaGetSymbolAddress((void**)&qkv, g_qkv);
    cudaGetSymbolAddress((void**)&y,   g_y);
    cudaGetSymbolAddress((void**)&ff,  g_ff);

    embed_kernel<<<Rq, 256>>>(idx, tok_emb, x);

    for (int l = 0; l < Lq; l++) {
        // h = LN1(x)
        ln_kernel<<<Rq, 256>>>(x, ln1_s + (size_t)l * Dq, ln1_b + (size_t)l * Dq, ln);
        // qkv = h @ Wqkv + bqkv   [2048,1024]x[1024,3072]
        tgemm_kernel<0><<<dim3(3 * Dq / 128, Rq / 128), 256>>>(
            ln, qkv_w + (size_t)l * Dq * 3 * Dq, qkv_b + (size_t)l * 3 * Dq,
            qkv, Rq, 3 * Dq, Dq);
        // causal attention
        attn_kernel<<<dim3(Tq, Hq, Bq), 128>>>(qkv, y);
        // x += y @ Wo + bo
        tgemm_kernel<1><<<dim3(Dq / 128, Rq / 128), 256>>>(
            y, out_w + (size_t)l * Dq * Dq, out_b + (size_t)l * Dq,
            x, Rq, Dq, Dq);
        // h2 = LN2(x)
        ln_kernel<<<Rq, 256>>>(x, ln2_s + (size_t)l * Dq, ln2_b + (size_t)l * Dq, ln);
        // ff = gelu(h2 @ W1 + b1)   [2048,1024]x[1024,4096]
        tgemm_kernel<2><<<dim3(FFq / 128, Rq / 128), 256>>>(
            ln, mlp_w1 + (size_t)l * Dq * FFq, mlp_b1 + (size_t)l * FFq,
            ff, Rq, FFq, Dq);
        // x += ff @ W2 + b2   [2048,4096]x[4096,1024]
        tgemm_kernel<1><<<dim3(Dq / 128, Rq / 128), 256>>>(
            ff, mlp_w2 + (size_t)l * FFq * Dq, mlp_b2 + (size_t)l * Dq,
            x, Rq, Dq, FFq);
    }

    // final LN + head
    ln_kernel<<<Rq, 256>>>(x, lnf_s, lnf_b, ln);
    tgemm_kernel<0><<<dim3(Vq / 128, Rq / 128), 256>>>(
        ln, head_w, (const float*)nullptr, logits, Rq, Vq, Dq);
}

// round 4
// speedup vs baseline: 3.4460x; 2.2149x over previous
#include <cuda_runtime.h>
#include <math.h>
#include <math_constants.h>

// Problem constants
#define Bq  2
#define Tq  1024
#define Dq  1024
#define Hq  16
#define FFq 4096
#define Lq  8
#define Vq  32000
#define HDq 64
#define Rq  (Bq * Tq)   // 2048 rows

// ---------------------------------------------------------------------------
// Scratch (device globals; no runtime allocation allowed)
// ---------------------------------------------------------------------------
__device__ float g_x  [Rq * Dq];       // residual stream
__device__ float g_ln [Rq * Dq];       // layernorm output
__device__ float g_qkv[Rq * 3 * Dq];   // q|k|v
__device__ float g_y  [Rq * Dq];       // attention output
__device__ float g_ff [Rq * FFq];      // mlp hidden

// ---------------------------------------------------------------------------
// Block reductions
// ---------------------------------------------------------------------------
__device__ __forceinline__ float block_sum(float v, float* sh) {
    int lane = threadIdx.x & 31, w = threadIdx.x >> 5, nw = blockDim.x >> 5;
    #pragma unroll
    for (int o = 16; o; o >>= 1) v += __shfl_xor_sync(0xffffffffu, v, o);
    if (lane == 0) sh[w] = v;
    __syncthreads();
    if (w == 0) {
        v = (lane < nw) ? sh[lane] : 0.0f;
        #pragma unroll
        for (int o = 16; o; o >>= 1) v += __shfl_xor_sync(0xffffffffu, v, o);
        if (lane == 0) sh[0] = v;
    }
    __syncthreads();
    float r = sh[0];
    __syncthreads();
    return r;
}

// ---------------------------------------------------------------------------
// Embedding + sinusoidal PE
// ---------------------------------------------------------------------------
__global__ void embed_kernel(const int* __restrict__ idx,
                             const float* __restrict__ emb,
                             float* __restrict__ x) {
    int row = blockIdx.x;           // 0..2047  (b*T + t)
    int t   = row % Tq;
    int tok = idx[row];
    const float* er = emb + (size_t)tok * Dq;
    const float neg_log = -logf(10000.0f) / (float)Dq;
    for (int d = threadIdx.x; d < Dq; d += blockDim.x) {
        int i2 = d & ~1;                     // even index 0,2,4,...
        float freq = expf(neg_log * (float)i2);
        float ang  = (float)t * freq;
        float pe   = (d & 1) ? cosf(ang) : sinf(ang);
        x[(size_t)row * Dq + d] = er[d] + pe;
    }
}

// ---------------------------------------------------------------------------
// LayerNorm (two-pass, 256 threads, 4 elems/thread, D=1024)
// ---------------------------------------------------------------------------
__global__ void ln_kernel(const float* __restrict__ x,
                          const float* __restrict__ sc,
                          const float* __restrict__ bi,
                          float* __restrict__ out) {
    __shared__ float sh[32];
    int row = blockIdx.x;
    const float* xr = x + (size_t)row * Dq;
    float v[4];
    float lsum = 0.0f;
    #pragma unroll
    for (int i = 0; i < 4; i++) {
        v[i] = xr[threadIdx.x + i * 256];
        lsum += v[i];
    }
    float mean = block_sum(lsum, sh) * (1.0f / (float)Dq);
    float lsq = 0.0f;
    #pragma unroll
    for (int i = 0; i < 4; i++) {
        float d = v[i] - mean;
        lsq += d * d;
    }
    float var = block_sum(lsq, sh) * (1.0f / (float)Dq);
    float inv = rsqrtf(var + 1e-5f);
    #pragma unroll
    for (int i = 0; i < 4; i++) {
        int d = threadIdx.x + i * 256;
        out[(size_t)row * Dq + d] = (v[i] - mean) * inv * sc[d] + bi[d];
    }
}

// ---------------------------------------------------------------------------
// TF32 tensor-core GEMM with register-prefetch pipeline.
//   EPI 0: C = AB + bias ; EPI 1: C += AB + bias ; EPI 2: C = gelu(AB + bias)
// 128x128 tile, BK=32, 256 threads (8 warps, 2x4), warp tile 64x32,
// mma.sync.m16n8k8 tf32, fp32 accumulate, XOR-swizzled smem.
// ---------------------------------------------------------------------------
__device__ __forceinline__ unsigned f2tf(float x) {
    unsigned r;
    asm("cvt.rna.tf32.f32 %0, %1;" : "=r"(r) : "f"(x));
    return r;
}

__device__ __forceinline__ void mma_tf32(float c[4],
                                         unsigned a0, unsigned a1, unsigned a2, unsigned a3,
                                         unsigned b0, unsigned b1) {
    asm volatile(
        "mma.sync.aligned.m16n8k8.row.col.f32.tf32.tf32.f32 "
        "{%0,%1,%2,%3}, {%4,%5,%6,%7}, {%8,%9}, {%0,%1,%2,%3};"
        : "+f"(c[0]), "+f"(c[1]), "+f"(c[2]), "+f"(c[3])
        : "r"(a0), "r"(a1), "r"(a2), "r"(a3), "r"(b0), "r"(b1));
}

template <int EPI>
__global__ __launch_bounds__(256)
void tgemm_kernel(const float* __restrict__ A, const float* __restrict__ B,
                  const float* __restrict__ bias, float* __restrict__ C,
                  int M, int N, int K) {
    constexpr int BM = 128, BN = 128, BK = 32;
    __shared__ unsigned As[BK][BM];   // [k][m ^ ((k&3)<<3)]
    __shared__ unsigned Bs[BK][BN];   // [k][n ^ ((k&3)<<3)]

    int tid  = threadIdx.x;
    int lane = tid & 31;
    int warp = tid >> 5;
    int g    = lane >> 2;       // group 0..7
    int tig  = lane & 3;        // thread-in-group 0..3
    int sw   = tig << 3;        // fragment XOR swizzle
    int wm   = warp & 1;        // warp M index
    int wn   = warp >> 1;       // warp N index
    int rm   = wm * 64;
    int cn   = wn * 32;

    const float* Ab = A + (size_t)(blockIdx.y * BM) * K;
    const float* Bb = B + (size_t)(blockIdx.x) * BN;

    float acc[4][4][4];
    #pragma unroll
    for (int mi = 0; mi < 4; mi++)
        #pragma unroll
        for (int ni = 0; ni < 4; ni++)
            #pragma unroll
            for (int c = 0; c < 4; c++) acc[mi][ni][c] = 0.0f;

    // per-thread gmem addressing (constant across tiles)
    int am[4], ak[4], bk[4], bc[4];
    #pragma unroll
    for (int i = 0; i < 4; i++) {
        int lin = tid + i * 256;
        am[i] = lin >> 3;
        ak[i] = (lin & 7) * 4;
        bk[i] = lin >> 5;
        bc[i] = (lin & 31) * 4;
    }

    float4 areg[4], breg[4];
    // prologue: load tile 0
    #pragma unroll
    for (int i = 0; i < 4; i++) {
        areg[i] = *(const float4*)(Ab + (size_t)am[i] * K + ak[i]);
        breg[i] = *(const float4*)(Bb + (size_t)bk[i] * N + bc[i]);
    }

    for (int kt = 0; kt < K; kt += BK) {
        // ---- store staged regs to smem (convert to tf32) ----
        #pragma unroll
        for (int i = 0; i < 4; i++) {
            int m  = am[i], kq = ak[i];
            As[kq + 0][m ^ 0 ] = f2tf(areg[i].x);
            As[kq + 1][m ^ 8 ] = f2tf(areg[i].y);
            As[kq + 2][m ^ 16] = f2tf(areg[i].z);
            As[kq + 3][m ^ 24] = f2tf(areg[i].w);
            int kk = bk[i], c4 = bc[i];
            uint4 u;
            u.x = f2tf(breg[i].x); u.y = f2tf(breg[i].y);
            u.z = f2tf(breg[i].z); u.w = f2tf(breg[i].w);
            *(uint4*)&Bs[kk][c4 ^ ((kk & 3) << 3)] = u;
        }
        __syncthreads();

        // ---- prefetch next tile into regs (latency hidden under compute) ----
        if (kt + BK < K) {
            #pragma unroll
            for (int i = 0; i < 4; i++) {
                areg[i] = *(const float4*)(Ab + (size_t)am[i] * K + kt + BK + ak[i]);
                breg[i] = *(const float4*)(Bb + (size_t)(kt + BK + bk[i]) * N + bc[i]);
            }
        }

        // ---- compute: 4 k-steps of 8 ----
        #pragma unroll
        for (int ks = 0; ks < 4; ks++) {
            int k0 = ks * 8;
            unsigned af[4][4], bf[4][2];
            #pragma unroll
            for (int mi = 0; mi < 4; mi++) {
                int m1 = rm + mi * 16 + g;
                int m2 = m1 + 8;
                af[mi][0] = As[k0 + tig    ][m1 ^ sw];
                af[mi][1] = As[k0 + tig    ][m2 ^ sw];
                af[mi][2] = As[k0 + tig + 4][m1 ^ sw];
                af[mi][3] = As[k0 + tig + 4][m2 ^ sw];
            }
            #pragma unroll
            for (int ni = 0; ni < 4; ni++) {
                int nb = cn + ni * 8 + g;
                bf[ni][0] = Bs[k0 + tig    ][nb ^ sw];
                bf[ni][1] = Bs[k0 + tig + 4][nb ^ sw];
            }
            #pragma unroll
            for (int mi = 0; mi < 4; mi++)
                #pragma unroll
                for (int ni = 0; ni < 4; ni++)
                    mma_tf32(acc[mi][ni],
                             af[mi][0], af[mi][1], af[mi][2], af[mi][3],
                             bf[ni][0], bf[ni][1]);
        }
        __syncthreads();
    }

    // ---- epilogue ----
    #pragma unroll
    for (int ni = 0; ni < 4; ni++) {
        int gc = blockIdx.x * BN + cn + ni * 8 + 2 * tig;
        float bv0 = bias ? bias[gc]     : 0.0f;
        float bv1 = bias ? bias[gc + 1] : 0.0f;
        #pragma unroll
        for (int mi = 0; mi < 4; mi++) {
            int gr1 = blockIdx.y * BM + rm + mi * 16 + g;
            int gr2 = gr1 + 8;
            float v00 = acc[mi][ni][0] + bv0;
            float v01 = acc[mi][ni][1] + bv1;
            float v10 = acc[mi][ni][2] + bv0;
            float v11 = acc[mi][ni][3] + bv1;
            float* p1 = C + (size_t)gr1 * N + gc;
            float* p2 = C + (size_t)gr2 * N + gc;
            if (EPI == 0) {
                *(float2*)p1 = make_float2(v00, v01);
                *(float2*)p2 = make_float2(v10, v11);
            } else if (EPI == 1) {
                float2 o1 = *(const float2*)p1;
                float2 o2 = *(const float2*)p2;
                *(float2*)p1 = make_float2(o1.x + v00, o1.y + v01);
                *(float2*)p2 = make_float2(o2.x + v10, o2.y + v11);
            } else {
                const float inv_sqrt2 = 0.70710678118654752f;
                *(float2*)p1 = make_float2(
                    0.5f * v00 * (1.0f + erff(v00 * inv_sqrt2)),
                    0.5f * v01 * (1.0f + erff(v01 * inv_sqrt2)));
                *(float2*)p2 = make_float2(
                    0.5f * v10 * (1.0f + erff(v10 * inv_sqrt2)),
                    0.5f * v11 * (1.0f + erff(v11 * inv_sqrt2)));
            }
        }
    }
}

// ---------------------------------------------------------------------------
// Flash-style causal attention.
// One CTA per (64-query block, head, batch). 256 threads = 8 warps.
// Warp w owns query rows w*8..w*8+7; lane owns key/val cols {lane, lane+32}.
// K/V staged in smem tiles of 64 (row pad 68 -> conflict-free LDS).
// Online softmax (running max/sum) per row; P via warp-private smem.
// ---------------------------------------------------------------------------
#define APAD 68

__global__ __launch_bounds__(256)
void attn2_kernel(const float* __restrict__ qkv, float* __restrict__ y) {
    extern __shared__ float sm[];
    float* Qs = sm;                   // [64][68]
    float* Ks = sm + 64 * APAD;       // [64][68]
    float* Vs = sm + 2 * 64 * APAD;   // [64][68]
    float* Ps = sm + 3 * 64 * APAD;   // [64][68]  (row = w*8+r)

    int qb = blockIdx.x, h = blockIdx.y, b = blockIdx.z;
    int tid = threadIdx.x;
    int lane = tid & 31, w = tid >> 5;

    const size_t rowstride = 3 * Dq;
    const float* qbase = qkv + ((size_t)(b * Tq + qb * 64)) * rowstride + h * HDq;

    // load Q block (scaled by 1/sqrt(64))
    #pragma unroll
    for (int i = 0; i < 4; i++) {
        int f = tid + i * 256;          // 0..1023 float4 slots
        int r = f >> 4, c4 = (f & 15) * 4;
        float4 v = *(const float4*)(qbase + (size_t)r * rowstride + c4);
        float* dst = Qs + r * APAD + c4;
        dst[0] = v.x * 0.125f; dst[1] = v.y * 0.125f;
        dst[2] = v.z * 0.125f; dst[3] = v.w * 0.125f;
    }

    float out0[8], out1[8], mrow[8], lrow[8];
    #pragma unroll
    for (int r = 0; r < 8; r++) {
        out0[r] = 0.0f; out1[r] = 0.0f;
        mrow[r] = -CUDART_INF_F; lrow[r] = 0.0f;
    }

    for (int kt = 0; kt <= qb; kt++) {
        __syncthreads();   // Q ready (first iter) / previous tile fully consumed
        // stage K and V tiles
        const float* kbase = qkv + ((size_t)(b * Tq + kt * 64)) * rowstride + Dq + h * HDq;
        const float* vbase = kbase + Dq;
        #pragma unroll
        for (int i = 0; i < 4; i++) {
            int f = tid + i * 256;
            int r = f >> 4, c4 = (f & 15) * 4;
            *(float4*)(Ks + r * APAD + c4) = *(const float4*)(kbase + (size_t)r * rowstride + c4);
            *(float4*)(Vs + r * APAD + c4) = *(const float4*)(vbase + (size_t)r * rowstride + c4);
        }
        __syncthreads();

        // ---- scores: s[r][c] for c in {lane, lane+32} ----
        float s0[8], s1[8];
        #pragma unroll
        for (int r = 0; r < 8; r++) { s0[r] = 0.0f; s1[r] = 0.0f; }
        const float4* K0 = (const float4*)(Ks + lane * APAD);
        const float4* K1 = (const float4*)(Ks + (lane + 32) * APAD);
        #pragma unroll
        for (int j = 0; j < 16; j++) {
            float4 k0 = K0[j], k1 = K1[j];
            #pragma unroll
            for (int r = 0; r < 8; r++) {
                float4 qv = *(const float4*)(Qs + (w * 8 + r) * APAD + j * 4);
                s0[r] += qv.x * k0.x + qv.y * k0.y + qv.z * k0.z + qv.w * k0.w;
                s1[r] += qv.x * k1.x + qv.y * k1.y + qv.z * k1.z + qv.w * k1.w;
            }
        }

        bool diag = (kt == qb);
        #pragma unroll
        for (int r = 0; r < 8; r++) {
            int rloc = w * 8 + r;
            float a0 = s0[r], a1 = s1[r];
            if (diag) {
                if (lane      > rloc) a0 = -CUDART_INF_F;
                if (lane + 32 > rloc) a1 = -CUDART_INF_F;
            }
            // row max
            float mx = fmaxf(a0, a1);
            #pragma unroll
            for (int o = 16; o; o >>= 1) mx = fmaxf(mx, __shfl_xor_sync(0xffffffffu, mx, o));
            float mnew = fmaxf(mrow[r], mx);
            float corr = __expf(mrow[r] - mnew);
            float p0 = __expf(a0 - mnew);
            float p1 = __expf(a1 - mnew);
            float ps = p0 + p1;
            #pragma unroll
            for (int o = 16; o; o >>= 1) ps += __shfl_xor_sync(0xffffffffu, ps, o);
            lrow[r] = lrow[r] * corr + ps;
            out0[r] *= corr; out1[r] *= corr;
            mrow[r] = mnew;
            Ps[(w * 8 + r) * APAD + lane]      = p0;
            Ps[(w * 8 + r) * APAD + lane + 32] = p1;
        }
        __syncwarp();

        // ---- P @ V: out[r][d], d in {lane, lane+32} ----
        #pragma unroll
        for (int c4 = 0; c4 < 16; c4++) {
            float v0[4], v1[4];
            #pragma unroll
            for (int i = 0; i < 4; i++) {
                v0[i] = Vs[(c4 * 4 + i) * APAD + lane];
                v1[i] = Vs[(c4 * 4 + i) * APAD + lane + 32];
            }
            #pragma unroll
            for (int r = 0; r < 8; r++) {
                float4 p = *(const float4*)(Ps + (w * 8 + r) * APAD + c4 * 4);
                out0[r] += p.x * v0[0] + p.y * v0[1] + p.z * v0[2] + p.w * v0[3];
                out1[r] += p.x * v1[0] + p.y * v1[1] + p.z * v1[2] + p.w * v1[3];
            }
        }
        __syncwarp();
    }

    // write output
    #pragma unroll
    for (int r = 0; r < 8; r++) {
        float inv = 1.0f / lrow[r];
        size_t row = (size_t)(b * Tq + qb * 64 + w * 8 + r);
        float* yr = y + row * Dq + h * HDq;
        yr[lane]      = out0[r] * inv;
        yr[lane + 32] = out1[r] * inv;
    }
}

// ---------------------------------------------------------------------------
// Launch
// ---------------------------------------------------------------------------
extern "C" void kernel_launch(void* const* d_in, const int* in_sizes, int n_in,
                              void* d_out, int out_size) {
    const int*   idx     = (const int*)  d_in[0];
    const float* tok_emb = (const float*)d_in[1];
    const float* ln1_s   = (const float*)d_in[2];
    const float* ln1_b   = (const float*)d_in[3];
    const float* qkv_w   = (const float*)d_in[4];
    const float* qkv_b   = (const float*)d_in[5];
    const float* out_w   = (const float*)d_in[6];
    const float* out_b   = (const float*)d_in[7];
    const float* ln2_s   = (const float*)d_in[8];
    const float* ln2_b   = (const float*)d_in[9];
    const float* mlp_w1  = (const float*)d_in[10];
    const float* mlp_b1  = (const float*)d_in[11];
    const float* mlp_w2  = (const float*)d_in[12];
    const float* mlp_b2  = (const float*)d_in[13];
    const float* lnf_s   = (const float*)d_in[14];
    const float* lnf_b   = (const float*)d_in[15];
    const float* head_w  = (const float*)d_in[16];
    float* logits = (float*)d_out;

    float *x, *ln, *qkv, *y, *ff;
    cudaGetSymbolAddress((void**)&x,   g_x);
    cudaGetSymbolAddress((void**)&ln,  g_ln);
    cudaGetSymbolAddress((void**)&qkv, g_qkv);
    cudaGetSymbolAddress((void**)&y,   g_y);
    cudaGetSymbolAddress((void**)&ff,  g_ff);

    const int attn_smem = 4 * 64 * APAD * (int)sizeof(float);  // ~69.6 KB
    cudaFuncSetAttribute(attn2_kernel,
                         cudaFuncAttributeMaxDynamicSharedMemorySize, attn_smem);

    embed_kernel<<<Rq, 256>>>(idx, tok_emb, x);

    for (int l = 0; l < Lq; l++) {
        ln_kernel<<<Rq, 256>>>(x, ln1_s + (size_t)l * Dq, ln1_b + (size_t)l * Dq, ln);
        tgemm_kernel<0><<<dim3(3 * Dq / 128, Rq / 128), 256>>>(
            ln, qkv_w + (size_t)l * Dq * 3 * Dq, qkv_b + (size_t)l * 3 * Dq,
            qkv, Rq, 3 * Dq, Dq);
        attn2_kernel<<<dim3(Tq / 64, Hq, Bq), 256, attn_smem>>>(qkv, y);
        tgemm_kernel<1><<<dim3(Dq / 128, Rq / 128), 256>>>(
            y, out_w + (size_t)l * Dq * Dq, out_b + (size_t)l * Dq,
            x, Rq, Dq, Dq);
        ln_kernel<<<Rq, 256>>>(x, ln2_s + (size_t)l * Dq, ln2_b + (size_t)l * Dq, ln);
        tgemm_kernel<2><<<dim3(FFq / 128, Rq / 128), 256>>>(
            ln, mlp_w1 + (size_t)l * Dq * FFq, mlp_b1 + (size_t)l * FFq,
            ff, Rq, FFq, Dq);
        tgemm_kernel<1><<<dim3(Dq / 128, Rq / 128), 256>>>(
            ff, mlp_w2 + (size_t)l * FFq * Dq, mlp_b2 + (size_t)l * Dq,
            x, Rq, Dq, FFq);
    }

    ln_kernel<<<Rq, 256>>>(x, lnf_s, lnf_b, ln);
    tgemm_kernel<0><<<dim3(Vq / 128, Rq / 128), 256>>>(
        ln, head_w, (const float*)nullptr, logits, Rq, Vq, Dq);
}